// round 10
// baseline (speedup 1.0000x reference)
#include <cuda_runtime.h>
#include <math_constants.h>

#define VOCAB   50257
#define NBEAM   8
#define TOPK    8
#define HIST    128
#define PARTS   32
#define CHUNK   1571            /* ceil(50257/32) */
#define TPB     256
#define NV      7               /* ceil(CHUNK/TPB) */
#define ROWBLK  (PARTS*NBEAM)   /* 256 */
#define NBLOCKS 1184            /* 148 SMs * 8 CTAs — one persistent wave */
#define NTILES  32768           /* 32*REST4/TPB gather tiles */
#define REST4   262144          /* KV2*HEADS*SEQ*HDIM/4 */
#define KV_TOTAL 268435456LL

__device__ float g_pm[NBEAM * PARTS];
__device__ float g_ps[NBEAM * PARTS];
__device__ float g_pv[NBEAM * PARTS * TOPK];
__device__ int   g_pi[NBEAM * PARTS * TOPK];
__device__ int   g_bi[NBEAM];
__device__ int   g_cnt;     // rowtop blocks done   (self-resets)
__device__ int   g_cnt2;    // all blocks done      (self-resets)
__device__ int   g_flag;    // indices-ready        (self-resets)

__global__ void __launch_bounds__(TPB, 8)   // regs<=32 -> all 1184 CTAs co-resident
k_fused(const float* __restrict__ logits,
        const float* __restrict__ prev,
        const int*   __restrict__ save_id,
        const float4* __restrict__ kv,
        float4* __restrict__ out) {
    const int bid = blockIdx.x;
    const int tid = threadIdx.x, lane = tid & 31, wid = tid >> 5;

    // =====================================================================
    // Role A: blocks 0..255 compute per-(part,row) lse + top-8 partials
    // =====================================================================
    if (bid < ROWBLK) {
        const int part = bid & (PARTS - 1), b = bid >> 5;
        const int base = part * CHUNK;
        const float* __restrict__ row = logits + (long long)b * VOCAB;

        // ---- batched predicated loads (branch-free, MLP=NV) ----
        float val[NV]; int idx[NV];
        #pragma unroll
        for (int j = 0; j < NV; j++) {
            const int i = tid + j * TPB;
            const int g = base + i;
            const bool ok = (i < CHUNK) & (g < VOCAB);
            val[j] = ok ? __ldg(row + g) : -CUDART_INF_F;
            idx[j] = ok ? g : 0x7fffffff;
        }

        // ---- branch-free two-pass lse over registers ----
        float m = val[0];
        #pragma unroll
        for (int j = 1; j < NV; j++) m = fmaxf(m, val[j]);
        float s = 0.f;
        #pragma unroll
        for (int j = 0; j < NV; j++) s += __expf(val[j] - m);

        #pragma unroll
        for (int off = 16; off; off >>= 1) {
            float om = __shfl_down_sync(0xffffffffu, m, off);
            float os = __shfl_down_sync(0xffffffffu, s, off);
            if (om > m)                  { s = s * __expf(m - om) + os; m = om; }
            else if (om > -CUDART_INF_F) { s += os * __expf(om - m); }
        }
        __shared__ float swm[8], sws[8];
        if (lane == 0) { swm[wid] = m; sws[wid] = s; }

        // ---- stable in-place desc sort of the 7 registers ----
        #pragma unroll
        for (int a = 0; a < NV - 1; a++) {
            #pragma unroll
            for (int q = 0; q < NV - 1 - a; q++) {
                if (val[q + 1] > val[q]) {
                    float tv = val[q]; val[q] = val[q + 1]; val[q + 1] = tv;
                    int   ti = idx[q]; idx[q] = idx[q + 1]; idx[q + 1] = ti;
                }
            }
        }

        __syncthreads();
        if (wid == 0) {
            float mm = (lane < 8) ? swm[lane] : -CUDART_INF_F;
            float ss = (lane < 8) ? sws[lane] : 0.f;
            #pragma unroll
            for (int off = 4; off; off >>= 1) {
                float om = __shfl_down_sync(0xffffffffu, mm, off);
                float os = __shfl_down_sync(0xffffffffu, ss, off);
                if (om > mm)                  { ss = ss * __expf(mm - om) + os; mm = om; }
                else if (om > -CUDART_INF_F)  { ss += os * __expf(om - mm); }
            }
            if (lane == 0) { g_pm[b * PARTS + part] = mm; g_ps[b * PARTS + part] = ss; }
        }

        // ---- warp top-8 pop-merge: winners go straight to smem ----
        __shared__ float sw_v[8 * TOPK];
        __shared__ int   sw_i[8 * TOPK];
        #pragma unroll
        for (int k = 0; k < TOPK; k++) {
            float bv = val[0]; int bidx = idx[0];
            #pragma unroll
            for (int off = 16; off; off >>= 1) {
                float ov = __shfl_down_sync(0xffffffffu, bv, off);
                int   oi = __shfl_down_sync(0xffffffffu, bidx, off);
                if (ov > bv || (ov == bv && oi < bidx)) { bv = ov; bidx = oi; }
            }
            bv   = __shfl_sync(0xffffffffu, bv, 0);
            bidx = __shfl_sync(0xffffffffu, bidx, 0);
            if (idx[0] == bidx && val[0] == bv) {
                #pragma unroll
                for (int q = 0; q < NV - 1; q++) { val[q] = val[q + 1]; idx[q] = idx[q + 1]; }
                val[NV - 1] = -CUDART_INF_F; idx[NV - 1] = 0x7fffffff;
            }
            if (lane == 0) { sw_v[wid * TOPK + k] = bv; sw_i[wid * TOPK + k] = bidx; }
        }
        __syncthreads();

        // ---- block merge of 8 warp lists via warp 0 ----
        if (wid == 0) {
            float lv[TOPK]; int li[TOPK];
            #pragma unroll
            for (int j = 0; j < TOPK; j++) {
                lv[j] = (lane < 8) ? sw_v[lane * TOPK + j] : -CUDART_INF_F;
                li[j] = (lane < 8) ? sw_i[lane * TOPK + j] : 0x7fffffff;
            }
            #pragma unroll
            for (int k = 0; k < TOPK; k++) {
                float bv = lv[0]; int bidx = li[0];
                #pragma unroll
                for (int off = 16; off; off >>= 1) {
                    float ov = __shfl_down_sync(0xffffffffu, bv, off);
                    int   oi = __shfl_down_sync(0xffffffffu, bidx, off);
                    if (ov > bv || (ov == bv && oi < bidx)) { bv = ov; bidx = oi; }
                }
                bv   = __shfl_sync(0xffffffffu, bv, 0);
                bidx = __shfl_sync(0xffffffffu, bidx, 0);
                if (li[0] == bidx && lv[0] == bv) {
                    #pragma unroll
                    for (int q = 0; q < TOPK - 1; q++) { lv[q] = lv[q + 1]; li[q] = li[q + 1]; }
                    lv[TOPK - 1] = -CUDART_INF_F; li[TOPK - 1] = 0x7fffffff;
                }
                if (lane == 0) {
                    g_pv[(b * PARTS + part) * TOPK + k] = bv;
                    g_pi[(b * PARTS + part) * TOPK + k] = bidx;
                }
            }
        }

        // ---- last rowtop block: combine + raise flag ----
        __shared__ int s_last;
        if (tid == 0) {
            __threadfence();
            int c = atomicAdd(&g_cnt, 1);
            s_last = (c == ROWBLK - 1);
            if (s_last) g_cnt = 0;
        }
        __syncthreads();
        if (s_last) {
            __shared__ float sh_prob[NBEAM * TOPK];
            __shared__ int   sh_idx[NBEAM * TOPK];
            __shared__ int   s_bi[NBEAM], s_tbi[NBEAM];
            __shared__ float s_sel[NBEAM];

            const int w = wid;  // 8 warps = 8 beam rows
            {
                float mm = g_pm[w * PARTS + lane];
                float ss = g_ps[w * PARTS + lane];
                #pragma unroll
                for (int off = 16; off; off >>= 1) {
                    float om = __shfl_down_sync(0xffffffffu, mm, off);
                    float os = __shfl_down_sync(0xffffffffu, ss, off);
                    if (om > mm)                  { ss = ss * __expf(mm - om) + os; mm = om; }
                    else if (om > -CUDART_INF_F)  { ss += os * __expf(om - mm); }
                }
                float lse = __shfl_sync(0xffffffffu, mm + logf(ss), 0);

                float cv[8]; int ci[8]; bool used[8];
                #pragma unroll
                for (int j = 0; j < 8; j++) {
                    int c2 = w * PARTS * TOPK + j * 32 + lane;
                    cv[j] = g_pv[c2]; ci[j] = g_pi[c2]; used[j] = false;
                }
                for (int k = 0; k < TOPK; k++) {
                    float bv = -CUDART_INF_F; int bidx = 0x7fffffff;
                    #pragma unroll
                    for (int j = 0; j < 8; j++)
                        if (!used[j] && (cv[j] > bv || (cv[j] == bv && ci[j] < bidx))) { bv = cv[j]; bidx = ci[j]; }
                    #pragma unroll
                    for (int off = 16; off; off >>= 1) {
                        float ov = __shfl_down_sync(0xffffffffu, bv, off);
                        int   oi = __shfl_down_sync(0xffffffffu, bidx, off);
                        if (ov > bv || (ov == bv && oi < bidx)) { bv = ov; bidx = oi; }
                    }
                    bv   = __shfl_sync(0xffffffffu, bv, 0);
                    bidx = __shfl_sync(0xffffffffu, bidx, 0);
                    #pragma unroll
                    for (int j = 0; j < 8; j++)
                        if (cv[j] == bv && ci[j] == bidx) used[j] = true;
                    if (lane == 0) { sh_prob[w * TOPK + k] = bv - lse; sh_idx[w * TOPK + k] = bidx; }
                }
            }
            __syncthreads();

            // final 64-candidate top-8 (val desc, flat idx asc = jax order)
            if (wid == 0) {
                const int j0 = lane * 2, j1 = lane * 2 + 1;
                float c0 = sh_prob[j0] + __ldg(prev + (j0 >> 3));
                float c1 = sh_prob[j1] + __ldg(prev + (j1 >> 3));
                bool u0 = false, u1 = false;
                for (int k = 0; k < NBEAM; k++) {
                    float bv = -CUDART_INF_F; int bj = 0x7fffffff;
                    if (!u0)                                       { bv = c0; bj = j0; }
                    if (!u1 && (c1 > bv || (c1 == bv && j1 < bj))) { bv = c1; bj = j1; }
                    #pragma unroll
                    for (int off = 16; off; off >>= 1) {
                        float ov = __shfl_down_sync(0xffffffffu, bv, off);
                        int   oj = __shfl_down_sync(0xffffffffu, bj, off);
                        if (ov > bv || (ov == bv && oj < bj)) { bv = ov; bj = oj; }
                    }
                    bv = __shfl_sync(0xffffffffu, bv, 0);
                    bj = __shfl_sync(0xffffffffu, bj, 0);
                    if (bj == j0) u0 = true;
                    if (bj == j1) u1 = true;
                    if (lane == 0) {
                        s_bi[k]  = bj >> 3;
                        s_tbi[k] = sh_idx[bj];
                        s_sel[k] = bv;
                        g_bi[k]  = bj >> 3;
                    }
                }
            }
            __syncthreads();

            float* o = (float*)out + KV_TOTAL;
            for (int t = tid; t < NBEAM * (HIST + 1); t += TPB) {
                int ob = t / (HIST + 1), h = t % (HIST + 1);
                int vv = (h < HIST) ? save_id[s_bi[ob] * HIST + h] : s_tbi[ob];
                o[t]   = (float)vv;
            }
            if (tid < NBEAM) {
                o[NBEAM * (HIST + 1) + tid]         = s_sel[tid];
                o[NBEAM * (HIST + 1) + NBEAM + tid] = (float)s_tbi[tid];
            }
            if (tid == 0) {
                o[NBEAM * (HIST + 1) + 2 * NBEAM] = (float)s_tbi[0];
                __threadfence();
                *((volatile int*)&g_flag) = 1;     // release: g_bi visible
            }
        }
    }

    // =====================================================================
    // Role B: wait for indices, then persistent grid-stride gather
    // =====================================================================
    __shared__ int sh_gbi[NBEAM];
    if (tid == 0) {
        while (*((volatile int*)&g_flag) == 0) { __nanosleep(64); }
        __threadfence();                          // acquire
        #pragma unroll
        for (int ob = 0; ob < NBEAM; ob++)
            sh_gbi[ob] = *((volatile int*)&g_bi[ob]);
    }
    __syncthreads();

    for (int tile = bid; tile < NTILES; tile += NBLOCKS) {
        const long long t = (long long)tile * TPB + tid;   // [0, 32*REST4)
        const int l = (int)(t >> 18);
        const int r = (int)(t & (REST4 - 1));
        const long long base = (((long long)l * NBEAM) << 18) + r;

        // two batches of 4 to fit the 32-reg cap; L1 dedups repeat beams
        #pragma unroll
        for (int h = 0; h < 2; h++) {
            float4 v[4];
            #pragma unroll
            for (int j = 0; j < 4; j++)
                v[j] = __ldg(&kv[base + ((long long)sh_gbi[h * 4 + j] << 18)]);
            #pragma unroll
            for (int j = 0; j < 4; j++)
                out[base + ((long long)(h * 4 + j) << 18)] = v[j];
        }
    }

    // ---- grid-done counter resets flag for next graph replay ----
    if (tid == 0) {
        int c = atomicAdd(&g_cnt2, 1);
        if (c == NBLOCKS - 1) { g_flag = 0; g_cnt2 = 0; }
    }
}

// ---------------------------------------------------------------------------
extern "C" void kernel_launch(void* const* d_in, const int* in_sizes, int n_in,
                              void* d_out, int out_size) {
    const float* kv      = (const float*)d_in[0];
    const float* logits  = (const float*)d_in[1];
    const int*   save_id = (const int*)d_in[2];
    const float* prev    = (const float*)d_in[3];

    k_fused<<<NBLOCKS, TPB>>>(logits, prev, save_id,
                              (const float4*)kv, (float4*)d_out);
}

// round 11
// speedup vs baseline: 1.2084x; 1.2084x over previous
#include <cuda_runtime.h>
#include <math_constants.h>

#define VOCAB   50257
#define NBEAM   8
#define TOPK    8
#define HIST    128
#define PARTS   32
#define CHUNK   1571            /* ceil(50257/32) */
#define TPB     256
#define NV      7               /* ceil(CHUNK/TPB) */
#define ROWBLK  (PARTS*NBEAM)   /* 256 */
#define REST4   262144          /* KV2*HEADS*SEQ*HDIM/4 */
#define KV_TOTAL 268435456LL

__device__ float g_pm[NBEAM * PARTS];
__device__ float g_ps[NBEAM * PARTS];
__device__ float g_pv[NBEAM * PARTS * TOPK];
__device__ int   g_pi[NBEAM * PARTS * TOPK];
__device__ int   g_bi[NBEAM];
__device__ int   g_cnt;     // rowtop blocks done (self-resets each run)

// ---------------------------------------------------------------------------
// Kernel 1: rowtop partials (256 blocks); last block runs the combine.
// ---------------------------------------------------------------------------
__global__ void __launch_bounds__(TPB)
k_front(const float* __restrict__ logits,
        const float* __restrict__ prev,
        const int*   __restrict__ save_id,
        float* __restrict__ out) {
    const int bid = blockIdx.x;
    const int tid = threadIdx.x, lane = tid & 31, wid = tid >> 5;
    const int part = bid & (PARTS - 1), b = bid >> 5;
    const int base = part * CHUNK;
    const float* __restrict__ row = logits + (long long)b * VOCAB;

    // ---- batched predicated loads (branch-free, MLP=NV) ----
    float val[NV]; int idx[NV];
    #pragma unroll
    for (int j = 0; j < NV; j++) {
        const int i = tid + j * TPB;
        const int g = base + i;
        const bool ok = (i < CHUNK) & (g < VOCAB);
        val[j] = ok ? __ldg(row + g) : -CUDART_INF_F;
        idx[j] = ok ? g : 0x7fffffff;
    }

    // ---- branch-free two-pass lse over registers ----
    float m = val[0];
    #pragma unroll
    for (int j = 1; j < NV; j++) m = fmaxf(m, val[j]);
    float s = 0.f;
    #pragma unroll
    for (int j = 0; j < NV; j++) s += __expf(val[j] - m);

    #pragma unroll
    for (int off = 16; off; off >>= 1) {
        float om = __shfl_down_sync(0xffffffffu, m, off);
        float os = __shfl_down_sync(0xffffffffu, s, off);
        if (om > m)                  { s = s * __expf(m - om) + os; m = om; }
        else if (om > -CUDART_INF_F) { s += os * __expf(om - m); }
    }
    __shared__ float swm[8], sws[8];
    if (lane == 0) { swm[wid] = m; sws[wid] = s; }

    // ---- stable in-place desc sort of the 7 registers ----
    // adjacent strict-> swaps keep ascending-index tie order (= jax top_k)
    #pragma unroll
    for (int a = 0; a < NV - 1; a++) {
        #pragma unroll
        for (int q = 0; q < NV - 1 - a; q++) {
            if (val[q + 1] > val[q]) {
                float tv = val[q]; val[q] = val[q + 1]; val[q + 1] = tv;
                int   ti = idx[q]; idx[q] = idx[q + 1]; idx[q + 1] = ti;
            }
        }
    }

    __syncthreads();
    if (wid == 0) {
        float mm = (lane < 8) ? swm[lane] : -CUDART_INF_F;
        float ss = (lane < 8) ? sws[lane] : 0.f;
        #pragma unroll
        for (int off = 4; off; off >>= 1) {
            float om = __shfl_down_sync(0xffffffffu, mm, off);
            float os = __shfl_down_sync(0xffffffffu, ss, off);
            if (om > mm)                  { ss = ss * __expf(mm - om) + os; mm = om; }
            else if (om > -CUDART_INF_F)  { ss += os * __expf(om - mm); }
        }
        if (lane == 0) { g_pm[b * PARTS + part] = mm; g_ps[b * PARTS + part] = ss; }
    }

    // ---- warp top-8 pop-merge: winners straight to smem ----
    __shared__ float sw_v[8 * TOPK];
    __shared__ int   sw_i[8 * TOPK];
    #pragma unroll
    for (int k = 0; k < TOPK; k++) {
        float bv = val[0]; int bidx = idx[0];
        #pragma unroll
        for (int off = 16; off; off >>= 1) {
            float ov = __shfl_down_sync(0xffffffffu, bv, off);
            int   oi = __shfl_down_sync(0xffffffffu, bidx, off);
            if (ov > bv || (ov == bv && oi < bidx)) { bv = ov; bidx = oi; }
        }
        bv   = __shfl_sync(0xffffffffu, bv, 0);
        bidx = __shfl_sync(0xffffffffu, bidx, 0);
        if (idx[0] == bidx && val[0] == bv) {   // this lane's head won -> pop
            #pragma unroll
            for (int q = 0; q < NV - 1; q++) { val[q] = val[q + 1]; idx[q] = idx[q + 1]; }
            val[NV - 1] = -CUDART_INF_F; idx[NV - 1] = 0x7fffffff;
        }
        if (lane == 0) { sw_v[wid * TOPK + k] = bv; sw_i[wid * TOPK + k] = bidx; }
    }
    __syncthreads();

    // ---- block merge of 8 warp lists via warp 0 ----
    if (wid == 0) {
        float lv[TOPK]; int li[TOPK];
        #pragma unroll
        for (int j = 0; j < TOPK; j++) {
            lv[j] = (lane < 8) ? sw_v[lane * TOPK + j] : -CUDART_INF_F;
            li[j] = (lane < 8) ? sw_i[lane * TOPK + j] : 0x7fffffff;
        }
        #pragma unroll
        for (int k = 0; k < TOPK; k++) {
            float bv = lv[0]; int bidx = li[0];
            #pragma unroll
            for (int off = 16; off; off >>= 1) {
                float ov = __shfl_down_sync(0xffffffffu, bv, off);
                int   oi = __shfl_down_sync(0xffffffffu, bidx, off);
                if (ov > bv || (ov == bv && oi < bidx)) { bv = ov; bidx = oi; }
            }
            bv   = __shfl_sync(0xffffffffu, bv, 0);
            bidx = __shfl_sync(0xffffffffu, bidx, 0);
            if (li[0] == bidx && lv[0] == bv) {
                #pragma unroll
                for (int q = 0; q < TOPK - 1; q++) { lv[q] = lv[q + 1]; li[q] = li[q + 1]; }
                lv[TOPK - 1] = -CUDART_INF_F; li[TOPK - 1] = 0x7fffffff;
            }
            if (lane == 0) {
                g_pv[(b * PARTS + part) * TOPK + k] = bv;
                g_pi[(b * PARTS + part) * TOPK + k] = bidx;
            }
        }
    }

    // ---- last block: full combine + small outputs ----
    __shared__ int s_last;
    if (tid == 0) {
        __threadfence();
        int c = atomicAdd(&g_cnt, 1);
        s_last = (c == ROWBLK - 1);
        if (s_last) g_cnt = 0;              // reset for next graph replay
    }
    __syncthreads();
    if (!s_last) return;

    __shared__ float sh_prob[NBEAM * TOPK];
    __shared__ int   sh_idx[NBEAM * TOPK];
    __shared__ int   s_bi[NBEAM], s_tbi[NBEAM];
    __shared__ float s_sel[NBEAM];

    const int w = wid;  // 8 warps = 8 beam rows
    {
        // row lse from 32 partials (one per lane)
        float mm = g_pm[w * PARTS + lane];
        float ss = g_ps[w * PARTS + lane];
        #pragma unroll
        for (int off = 16; off; off >>= 1) {
            float om = __shfl_down_sync(0xffffffffu, mm, off);
            float os = __shfl_down_sync(0xffffffffu, ss, off);
            if (om > mm)                  { ss = ss * __expf(mm - om) + os; mm = om; }
            else if (om > -CUDART_INF_F)  { ss += os * __expf(om - mm); }
        }
        float lse = __shfl_sync(0xffffffffu, mm + logf(ss), 0);

        // merge 256 candidates -> top-8 (8 per lane)
        float cv[8]; int ci[8]; bool used[8];
        #pragma unroll
        for (int j = 0; j < 8; j++) {
            int c2 = w * PARTS * TOPK + j * 32 + lane;
            cv[j] = g_pv[c2]; ci[j] = g_pi[c2]; used[j] = false;
        }
        for (int k = 0; k < TOPK; k++) {
            float bv = -CUDART_INF_F; int bidx = 0x7fffffff;
            #pragma unroll
            for (int j = 0; j < 8; j++)
                if (!used[j] && (cv[j] > bv || (cv[j] == bv && ci[j] < bidx))) { bv = cv[j]; bidx = ci[j]; }
            #pragma unroll
            for (int off = 16; off; off >>= 1) {
                float ov = __shfl_down_sync(0xffffffffu, bv, off);
                int   oi = __shfl_down_sync(0xffffffffu, bidx, off);
                if (ov > bv || (ov == bv && oi < bidx)) { bv = ov; bidx = oi; }
            }
            bv   = __shfl_sync(0xffffffffu, bv, 0);
            bidx = __shfl_sync(0xffffffffu, bidx, 0);
            #pragma unroll
            for (int j = 0; j < 8; j++)
                if (cv[j] == bv && ci[j] == bidx) used[j] = true;
            if (lane == 0) { sh_prob[w * TOPK + k] = bv - lse; sh_idx[w * TOPK + k] = bidx; }
        }
    }
    __syncthreads();

    // final 64-candidate top-8 (val desc, flat idx asc = jax order)
    if (wid == 0) {
        const int j0 = lane * 2, j1 = lane * 2 + 1;
        float c0 = sh_prob[j0] + __ldg(prev + (j0 >> 3));
        float c1 = sh_prob[j1] + __ldg(prev + (j1 >> 3));
        bool u0 = false, u1 = false;
        for (int k = 0; k < NBEAM; k++) {
            float bv = -CUDART_INF_F; int bj = 0x7fffffff;
            if (!u0)                                       { bv = c0; bj = j0; }
            if (!u1 && (c1 > bv || (c1 == bv && j1 < bj))) { bv = c1; bj = j1; }
            #pragma unroll
            for (int off = 16; off; off >>= 1) {
                float ov = __shfl_down_sync(0xffffffffu, bv, off);
                int   oj = __shfl_down_sync(0xffffffffu, bj, off);
                if (ov > bv || (ov == bv && oj < bj)) { bv = ov; bj = oj; }
            }
            bv = __shfl_sync(0xffffffffu, bv, 0);
            bj = __shfl_sync(0xffffffffu, bj, 0);
            if (bj == j0) u0 = true;
            if (bj == j1) u1 = true;
            if (lane == 0) {
                s_bi[k]  = bj >> 3;
                s_tbi[k] = sh_idx[bj];
                s_sel[k] = bv;
                g_bi[k]  = bj >> 3;
            }
        }
    }
    __syncthreads();

    float* o = out + KV_TOTAL;
    for (int t = tid; t < NBEAM * (HIST + 1); t += TPB) {
        int ob = t / (HIST + 1), h = t % (HIST + 1);
        int vv = (h < HIST) ? save_id[s_bi[ob] * HIST + h] : s_tbi[ob];
        o[t]   = (float)vv;
    }
    if (tid < NBEAM) {
        o[NBEAM * (HIST + 1) + tid]         = s_sel[tid];          // top_beam_prob
        o[NBEAM * (HIST + 1) + NBEAM + tid] = (float)s_tbi[tid];   // tbi
    }
    if (tid == 0)
        o[NBEAM * (HIST + 1) + 2 * NBEAM] = (float)s_tbi[0];       // max_logits_idx
}

// ---------------------------------------------------------------------------
// Kernel 2: KV gather — exact R6 version (best measured: 215.2us, 83% DRAM)
// ---------------------------------------------------------------------------
__global__ void __launch_bounds__(256) k_gather(const float4* __restrict__ kv,
                                                float4* __restrict__ out) {
    const long long t = (long long)blockIdx.x * blockDim.x + threadIdx.x;
    const int l = (int)(t >> 18);
    const int r = (int)(t & (REST4 - 1));
    const long long base = (((long long)l * NBEAM) << 18) + r;

    int bi[NBEAM];
    #pragma unroll
    for (int ob = 0; ob < NBEAM; ob++) bi[ob] = g_bi[ob];

    float4 v[NBEAM];
    #pragma unroll
    for (int ob = 0; ob < NBEAM; ob++)
        v[ob] = __ldg(&kv[base + ((long long)bi[ob] << 18)]);
    #pragma unroll
    for (int ob = 0; ob < NBEAM; ob++)
        out[base + ((long long)ob << 18)] = v[ob];
}

// ---------------------------------------------------------------------------
extern "C" void kernel_launch(void* const* d_in, const int* in_sizes, int n_in,
                              void* d_out, int out_size) {
    const float* kv      = (const float*)d_in[0];
    const float* logits  = (const float*)d_in[1];
    const int*   save_id = (const int*)d_in[2];
    const float* prev    = (const float*)d_in[3];
    float*       out     = (float*)d_out;

    k_front<<<ROWBLK, TPB>>>(logits, prev, save_id, out);
    k_gather<<<32768, 256>>>((const float4*)kv, (float4*)out);
}